// round 17
// baseline (speedup 1.0000x reference)
#include <cuda_runtime.h>
#include <cuda_fp16.h>
#include <stdint.h>

// ---------------- problem constants ----------------
#define NN   84
#define PP   3486
#define HSZ  2048
#define H2   1024
#define G3H  6144

// ---------------- device scratch ----------------
__device__ float g_gi[NN * G3H];
__device__ float g_gh[PP * G3H];      // GRU: fp16 view [PP,3H]; later f32 t/t2
__device__ float g_y [PP * HSZ];
__device__ double g_acc[6];
__device__ int   g_iu[PP];
__device__ int   g_ju[PP];
__device__ __half g_ahi[PP * HSZ];    // activation fp16 (doubles as hidden-state carry)
__device__ __half g_bWhh[G3H * HSZ];  // weight fp16 buffers (converted once upfront)
__device__ __half g_bW1[HSZ * HSZ];
__device__ __half g_bW2[H2 * HSZ];
__device__ __half g_bW3[H2 * H2];

// fast, overflow-safe activations
__device__ __forceinline__ float sigm_f(float x) {
    return 1.0f / (1.0f + __expf(-x));
}
__device__ __forceinline__ float tanh_f(float x) {
    float e = __expf(-2.0f * fabsf(x));
    float t = (1.0f - e) / (1.0f + e);
    return copysignf(t, x);
}

__device__ __forceinline__ uint32_t s2u(const void* p) {
    uint32_t a;
    asm("{ .reg .u64 t; cvta.to.shared.u64 t, %1; cvt.u32.u64 %0, t; }" : "=r"(a) : "l"(p));
    return a;
}

// 8 halves (uint4) -> 8 floats
__device__ __forceinline__ void h8_to_f(uint4 v, float* o) {
    float2 f;
    f = __half22float2(*(__half2*)&v.x); o[0] = f.x; o[1] = f.y;
    f = __half22float2(*(__half2*)&v.y); o[2] = f.x; o[3] = f.y;
    f = __half22float2(*(__half2*)&v.z); o[4] = f.x; o[5] = f.y;
    f = __half22float2(*(__half2*)&v.w); o[6] = f.x; o[7] = f.y;
}
// 8 floats -> uint4 of halves
__device__ __forceinline__ uint4 f_to_h8(const float* o) {
    union { __half2 h[4]; uint4 u; } r;
    r.h[0] = __floats2half2_rn(o[0], o[1]);
    r.h[1] = __floats2half2_rn(o[2], o[3]);
    r.h[2] = __floats2half2_rn(o[4], o[5]);
    r.h[3] = __floats2half2_rn(o[6], o[7]);
    return r.u;
}
__device__ __forceinline__ void conv8(const float4* __restrict__ in,
                                      uint4* __restrict__ out, int i8) {
    float4 a = in[i8 * 2], b = in[i8 * 2 + 1];
    float o[8] = {a.x, a.y, a.z, a.w, b.x, b.y, b.z, b.w};
    out[i8] = f_to_h8(o);
}

// ---------------- packed f32x2 helpers (for small f32 GEMM) ----------------
__device__ __forceinline__ unsigned long long pk2(float lo, float hi) {
    unsigned long long r;
    asm("mov.b64 %0, {%1, %2};" : "=l"(r) : "f"(lo), "f"(hi));
    return r;
}
__device__ __forceinline__ void fma2(unsigned long long& d,
                                     unsigned long long a, unsigned long long b) {
    asm("fma.rn.f32x2 %0, %1, %2, %0;" : "+l"(d) : "l"(a), "l"(b));
}
__device__ __forceinline__ float2 unpk2(unsigned long long v) {
    float lo, hi;
    asm("mov.b64 {%0, %1}, %2;" : "=f"(lo), "=f"(hi) : "l"(v));
    return make_float2(lo, hi);
}

// ---------------- one-shot init + weight converts (fused) ----------------
#define N8_WHH  (G3H * HSZ / 8)
#define N8_W1   (HSZ * HSZ / 8)
#define N8_W2   (H2 * HSZ / 8)
#define N8_W3   (H2 * H2 / 8)
#define N8_ALL  (N8_WHH + N8_W1 + N8_W2 + N8_W3)

__global__ void k_convall(const float4* __restrict__ Whh, const float4* __restrict__ W1,
                          const float4* __restrict__ W2, const float4* __restrict__ W3)
{
    int i = blockIdx.x * blockDim.x + threadIdx.x;
    if (i < 6) g_acc[i] = 0.0;
    if (i < NN * NN) {
        int r = i / NN, c = i % NN;
        if (c > r) {
            int p = r * (NN - 1) - r * (r - 1) / 2 + (c - r - 1);
            g_iu[p] = r;
            g_ju[p] = c;
        }
    }
    if (i < N8_WHH) {
        conv8(Whh, (uint4*)g_bWhh, i);
    } else if (i < N8_WHH + N8_W1) {
        conv8(W1, (uint4*)g_bW1, i - N8_WHH);
    } else if (i < N8_WHH + N8_W1 + N8_W2) {
        conv8(W2, (uint4*)g_bW2, i - N8_WHH - N8_W1);
    } else if (i < N8_ALL) {
        conv8(W3, (uint4*)g_bW3, i - N8_WHH - N8_W1 - N8_W2);
    }
}

// ---------------- activation convert (8 elems/thread) ----------------
__global__ void k_conva8(const float4* __restrict__ in, uint4* __restrict__ hi, int n8) {
    int i = blockIdx.x * blockDim.x + threadIdx.x;
    if (i < n8) conv8(in, hi, i);
}

// ================= fp16 single-pass mma.sync GEMM, BK=64 =================
// C[M,N] = A[M,K] @ B[N,K]^T + bias.  OUTH: store fp16 output (GRU gates).
// CTA 128(M)x128(N), BK=64, 128 threads, warp grid 2(M) x 2(N), warp tile 64x64.
// 3-stage cp.async ring, ONE __syncthreads per K-tile iteration. 2 CTAs/SM.
// Row pitch 144 B (128 data + 16 pad); 144 mod 128 = 16 -> ldmatrix conflict-free.
#define LDB          144
#define MAT_BYTES    (128 * LDB)      // 18432
#define OFF_B        MAT_BYTES
#define STAGE_BYTES  (2 * MAT_BYTES)  // 36864
#define NSTAGE       3
#define GSMEM        (NSTAGE * STAGE_BYTES)   // 110592

#define LDSM4(R, A) \
    asm volatile("ldmatrix.sync.aligned.m8n8.x4.shared.b16 {%0,%1,%2,%3}, [%4];" \
        : "=r"((R)[0]), "=r"((R)[1]), "=r"((R)[2]), "=r"((R)[3]) : "r"(A))
#define LDSM4P(R0, R1, A) \
    asm volatile("ldmatrix.sync.aligned.m8n8.x4.shared.b16 {%0,%1,%2,%3}, [%4];" \
        : "=r"((R0)[0]), "=r"((R0)[1]), "=r"((R1)[0]), "=r"((R1)[1]) : "r"(A))
#define MMA(D, Aa, Bb) \
    asm volatile("mma.sync.aligned.m16n8k16.row.col.f32.f16.f16.f32 " \
        "{%0,%1,%2,%3},{%4,%5,%6,%7},{%8,%9},{%0,%1,%2,%3};" \
        : "+f"((D)[0]), "+f"((D)[1]), "+f"((D)[2]), "+f"((D)[3]) \
        : "r"((Aa)[0]), "r"((Aa)[1]), "r"((Aa)[2]), "r"((Aa)[3]), \
          "r"((Bb)[0]), "r"((Bb)[1]))

__device__ __forceinline__ void g_issue(
    uint32_t sbase, int s,
    const __half* Ahi, const __half* Bhi,
    int m0, int n0, int M, int K, int kt, int tid)
{
    const uint32_t stg = sbase + s * STAGE_BYTES;
    // A: 128 rows x 8 chunks (16B) = 1024 chunks
#pragma unroll
    for (int i = 0; i < 8; i++) {
        int cid = tid + i * 128;
        int r   = cid >> 3;
        int ch  = cid & 7;
        int row = m0 + r;
        int sz  = (row < M) ? 16 : 0;
        if (row >= M) row = M - 1;
        const __half* gp = Ahi + (size_t)row * K + kt * 64 + ch * 8;
        uint32_t sa = stg + r * LDB + ch * 16;
        asm volatile("cp.async.cg.shared.global [%0], [%1], 16, %2;"
                     :: "r"(sa), "l"(gp), "r"(sz));
    }
    // B: 128 rows x 8 chunks = 1024 chunks
#pragma unroll
    for (int i = 0; i < 8; i++) {
        int cid = tid + i * 128;
        int r   = cid >> 3;
        int ch  = cid & 7;
        const __half* gp = Bhi + (size_t)(n0 + r) * K + kt * 64 + ch * 8;
        uint32_t sa = stg + OFF_B + r * LDB + ch * 16;
        asm volatile("cp.async.ca.shared.global [%0], [%1], 16;"
                     :: "r"(sa), "l"(gp));
    }
}

template <bool RELU, int SLOT, bool OUTH>
__global__ __launch_bounds__(128)
void k_bgemm(const __half* __restrict__ Ahi, const __half* __restrict__ Bhi,
             const float* __restrict__ bias, void* __restrict__ Cv,
             int M, int N, int K)
{
    extern __shared__ char smem[];
    const uint32_t sbase = s2u(smem);
    const int tid  = threadIdx.x;
    const int wid  = tid >> 5;
    const int lane = tid & 31;
    const int m0 = blockIdx.y * 128;
    const int n0 = blockIdx.x * 128;
    const int wm = wid & 1;
    const int wn = wid >> 1;

    float acc[4][8][4];
#pragma unroll
    for (int a = 0; a < 4; a++)
#pragma unroll
        for (int b = 0; b < 8; b++)
#pragma unroll
            for (int c = 0; c < 4; c++) acc[a][b][c] = 0.f;

    const int NKT = K >> 6;   // BK=64

    g_issue(sbase, 0, Ahi, Bhi, m0, n0, M, K, 0, tid);
    asm volatile("cp.async.commit_group;" ::: "memory");
    g_issue(sbase, 1, Ahi, Bhi, m0, n0, M, K, 1, tid);
    asm volatile("cp.async.commit_group;" ::: "memory");

    const uint32_t a_lane = (uint32_t)((wm * 64 + (lane & 15)) * LDB + (lane >> 4) * 16);
    const uint32_t b_lane = (uint32_t)(OFF_B + (wn * 64 + (lane >> 4) * 8 + (lane & 7)) * LDB
                                       + ((lane >> 3) & 1) * 16);

    for (int kt = 0; kt < NKT; kt++) {
        asm volatile("cp.async.wait_group 1;" ::: "memory");   // tile kt resident
        __syncthreads();                                       // stage (kt-1)%3 free
        if (kt + 2 < NKT)
            g_issue(sbase, (kt + 2) % NSTAGE, Ahi, Bhi, m0, n0, M, K, kt + 2, tid);
        asm volatile("cp.async.commit_group;" ::: "memory");

        const uint32_t sb = sbase + (kt % NSTAGE) * STAGE_BYTES;
#pragma unroll
        for (int k16 = 0; k16 < 4; k16++) {
            uint32_t ah[4][4];
#pragma unroll
            for (int mt = 0; mt < 4; mt++) {
                uint32_t aadr = sb + a_lane + mt * (16 * LDB) + k16 * 32;
                LDSM4(ah[mt], aadr);
            }
            uint32_t bh[8][2];
#pragma unroll
            for (int ntb = 0; ntb < 8; ntb += 2) {
                uint32_t badr = sb + b_lane + ntb * (8 * LDB) + k16 * 32;
                LDSM4P(bh[ntb], bh[ntb + 1], badr);
            }
#pragma unroll
            for (int mt = 0; mt < 4; mt++)
#pragma unroll
                for (int nt = 0; nt < 8; nt++)
                    MMA(acc[mt][nt], ah[mt], bh[nt]);
        }
    }

    // ---------------- epilogue ----------------
    double lsum = 0.0, lsq = 0.0;
    const int rb = m0 + wm * 64 + (lane >> 2);
    const int cb = n0 + wn * 64 + (lane & 3) * 2;
#pragma unroll
    for (int mt = 0; mt < 4; mt++) {
#pragma unroll
        for (int half = 0; half < 2; half++) {
            int r = rb + mt * 16 + half * 8;
            if (r < M) {
#pragma unroll
                for (int nt = 0; nt < 8; nt++) {
                    int c = cb + nt * 8;
                    float v0 = acc[mt][nt][half * 2]     + bias[c];
                    float v1 = acc[mt][nt][half * 2 + 1] + bias[c + 1];
                    if (RELU) { v0 = fmaxf(v0, 0.f); v1 = fmaxf(v1, 0.f); }
                    if (OUTH) {
                        __half* crow = (__half*)Cv + (size_t)r * N;
                        *(__half2*)(crow + c) = __floats2half2_rn(v0, v1);
                    } else {
                        float* crow = (float*)Cv + (size_t)r * N;
                        *(float2*)(crow + c) = make_float2(v0, v1);
                    }
                    if (SLOT >= 0) {
                        lsum += (double)v0 + (double)v1;
                        lsq  += (double)v0 * v0 + (double)v1 * v1;
                    }
                }
            }
        }
    }
    if (SLOT >= 0) {
#pragma unroll
        for (int off = 16; off; off >>= 1) {
            lsum += __shfl_down_sync(0xffffffffu, lsum, off);
            lsq  += __shfl_down_sync(0xffffffffu, lsq,  off);
        }
        if (lane == 0) {
            atomicAdd(&g_acc[SLOT * 2],     lsum);
            atomicAdd(&g_acc[SLOT * 2 + 1], lsq);
        }
    }
}

// ---------------- f32 SGEMM (small; GEMM1 only) ----------------
template <bool RELU, int SLOT>
__global__ __launch_bounds__(256)
void k_gemm(const float* __restrict__ A, const float* __restrict__ B,
            const float* __restrict__ bias, float* __restrict__ C,
            int M, int N, int K)
{
    __shared__ float As[16][132];
    __shared__ float Bs[16][132];
    const int tid = threadIdx.x;
    const int tx  = tid & 15;
    const int ty  = tid >> 4;
    const int m0  = blockIdx.y * 128;
    const int n0  = blockIdx.x * 128;

    unsigned long long acc[8][4];
#pragma unroll
    for (int i = 0; i < 8; i++)
#pragma unroll
        for (int j = 0; j < 4; j++) acc[i][j] = 0ULL;

    for (int kt = 0; kt < K; kt += 16) {
        __syncthreads();
#pragma unroll
        for (int q = 0; q < 2; q++) {
            int fi  = tid + q * 256;
            int row = fi >> 2;
            int kq  = fi & 3;
            float4 av = make_float4(0.f, 0.f, 0.f, 0.f);
            int gr = m0 + row;
            if (gr < M)
                av = *(const float4*)(A + (size_t)gr * K + kt + kq * 4);
            As[kq * 4 + 0][row] = av.x;
            As[kq * 4 + 1][row] = av.y;
            As[kq * 4 + 2][row] = av.z;
            As[kq * 4 + 3][row] = av.w;
            float4 bv = *(const float4*)(B + (size_t)(n0 + row) * K + kt + kq * 4);
            Bs[kq * 4 + 0][row] = bv.x;
            Bs[kq * 4 + 1][row] = bv.y;
            Bs[kq * 4 + 2][row] = bv.z;
            Bs[kq * 4 + 3][row] = bv.w;
        }
        __syncthreads();
#pragma unroll
        for (int kk = 0; kk < 16; kk++) {
            float4 a0 = *(const float4*)&As[kk][ty * 8];
            float4 a1 = *(const float4*)&As[kk][ty * 8 + 4];
            float4 b0 = *(const float4*)&Bs[kk][tx * 8];
            float4 b1 = *(const float4*)&Bs[kk][tx * 8 + 4];
            unsigned long long bp0 = pk2(b0.x, b0.y);
            unsigned long long bp1 = pk2(b0.z, b0.w);
            unsigned long long bp2 = pk2(b1.x, b1.y);
            unsigned long long bp3 = pk2(b1.z, b1.w);
            float av[8] = {a0.x, a0.y, a0.z, a0.w, a1.x, a1.y, a1.z, a1.w};
#pragma unroll
            for (int i = 0; i < 8; i++) {
                unsigned long long ap = pk2(av[i], av[i]);
                fma2(acc[i][0], ap, bp0);
                fma2(acc[i][1], ap, bp1);
                fma2(acc[i][2], ap, bp2);
                fma2(acc[i][3], ap, bp3);
            }
        }
    }
#pragma unroll
    for (int i = 0; i < 8; i++) {
        int r = m0 + ty * 8 + i;
        if (r < M) {
            float* crow = C + (size_t)r * N + n0 + tx * 8;
            const float* brow = bias + n0 + tx * 8;
#pragma unroll
            for (int j2 = 0; j2 < 4; j2++) {
                float2 v = unpk2(acc[i][j2]);
                float c0 = v.x + brow[j2 * 2];
                float c1 = v.y + brow[j2 * 2 + 1];
                if (RELU) { c0 = fmaxf(c0, 0.f); c1 = fmaxf(c1, 0.f); }
                crow[j2 * 2]     = c0;
                crow[j2 * 2 + 1] = c1;
            }
        }
    }
}

// ---------------- GRU elementwise combine, 8 elems/thread ----------------
template <int STEP>
__global__ void k_gru(const float* __restrict__ hin32, const __half* __restrict__ ghh,
                      uint4* __restrict__ ohi)
{
    int idx = blockIdx.x * blockDim.x + threadIdx.x;
    if (idx >= PP * (HSZ / 8)) return;
    int p = idx >> 8;
    int j = (idx & 255) * 8;
    int node = (STEP == 0) ? g_iu[p] : g_ju[p];
    const float* gi = g_gi + (size_t)node * G3H;
    const __half* gh = ghh + (size_t)p * G3H;

    float gr[8], gz[8], gn[8], hr[8], hz[8], hn[8], hv[8], o[8];
    {
        float4 a, b;
        a = *(const float4*)(gi + j);           b = *(const float4*)(gi + j + 4);
        gr[0]=a.x; gr[1]=a.y; gr[2]=a.z; gr[3]=a.w; gr[4]=b.x; gr[5]=b.y; gr[6]=b.z; gr[7]=b.w;
        a = *(const float4*)(gi + j + HSZ);     b = *(const float4*)(gi + j + HSZ + 4);
        gz[0]=a.x; gz[1]=a.y; gz[2]=a.z; gz[3]=a.w; gz[4]=b.x; gz[5]=b.y; gz[6]=b.z; gz[7]=b.w;
        a = *(const float4*)(gi + j + 2*HSZ);   b = *(const float4*)(gi + j + 2*HSZ + 4);
        gn[0]=a.x; gn[1]=a.y; gn[2]=a.z; gn[3]=a.w; gn[4]=b.x; gn[5]=b.y; gn[6]=b.z; gn[7]=b.w;
    }
    h8_to_f(*(const uint4*)(gh + j),           hr);
    h8_to_f(*(const uint4*)(gh + j + HSZ),     hz);
    h8_to_f(*(const uint4*)(gh + j + 2 * HSZ), hn);
    if (STEP == 0) {
        float4 a = *(const float4*)(hin32 + (size_t)p * HSZ + j);
        float4 b = *(const float4*)(hin32 + (size_t)p * HSZ + j + 4);
        hv[0]=a.x; hv[1]=a.y; hv[2]=a.z; hv[3]=a.w; hv[4]=b.x; hv[5]=b.y; hv[6]=b.z; hv[7]=b.w;
    } else {
        h8_to_f(ohi[idx], hv);
    }
#pragma unroll
    for (int e = 0; e < 8; e++) {
        float r = sigm_f(gr[e] + hr[e]);
        float z = sigm_f(gz[e] + hz[e]);
        float n = tanh_f(gn[e] + r * hn[e]);
        o[e] = (1.f - z) * n + z * hv[e];
    }
    ohi[idx] = f_to_h8(o);
}

// ---------------- full-tensor LayerNorm apply, 8 elems/thread ----------------
__global__ void k_norm(const float* __restrict__ buf, const float* __restrict__ w,
                       const float* __restrict__ b, int count8, int slot,
                       uint4* __restrict__ ohi)
{
    double sum = g_acc[slot * 2];
    double sq  = g_acc[slot * 2 + 1];
    double cnt = (double)count8 * 8.0;
    double mu  = sum / cnt;
    double var = sq / cnt - mu * mu;
    float rs  = rsqrtf((float)var + 1e-5f);
    float fmu = (float)mu;
    for (int i = blockIdx.x * blockDim.x + threadIdx.x; i < count8;
         i += gridDim.x * blockDim.x) {
        float o[8];
#pragma unroll
        for (int q = 0; q < 2; q++) {
            float4 v  = *(const float4*)(buf + i * 8 + q * 4);
            float4 ww = *(const float4*)(w   + i * 8 + q * 4);
            float4 bb = *(const float4*)(b   + i * 8 + q * 4);
            o[q*4+0] = (v.x - fmu) * rs * ww.x + bb.x;
            o[q*4+1] = (v.y - fmu) * rs * ww.y + bb.y;
            o[q*4+2] = (v.z - fmu) * rs * ww.z + bb.z;
            o[q*4+3] = (v.w - fmu) * rs * ww.w + bb.w;
        }
        ohi[i] = f_to_h8(o);
    }
}

// ---------------- final: fused LN3 + dot + sigmoid + symmetric write ----------------
__global__ void k_out(const float* __restrict__ h3, const float* __restrict__ lnw,
                      const float* __restrict__ lnb, const float* __restrict__ w4,
                      const float* __restrict__ b4, float* __restrict__ out)
{
    int gw   = (blockIdx.x * blockDim.x + threadIdx.x) >> 5;
    int lane = threadIdx.x & 31;
    if (gw >= PP) {
        int d = gw - PP;
        if (d < NN && lane == 0) out[d * NN + d] = 0.f;
        return;
    }
    double sum = g_acc[4];
    double sq  = g_acc[5];
    double cnt = (double)PP * (double)H2;
    double mu  = sum / cnt;
    double var = sq / cnt - mu * mu;
    float rs  = rsqrtf((float)var + 1e-5f);
    float fmu = (float)mu;

    const float* hr = h3  + (size_t)gw * H2;
    const float* wr = lnw + (size_t)gw * H2;
    const float* br = lnb + (size_t)gw * H2;
    float s = 0.f;
#pragma unroll
    for (int t = 0; t < H2 / 128; t++) {
        int off = (t * 32 + lane) * 4;
        float4 v  = *(const float4*)(hr + off);
        float4 ww = *(const float4*)(wr + off);
        float4 bb = *(const float4*)(br + off);
        float4 q  = *(const float4*)(w4 + off);
        s += ((v.x - fmu) * rs * ww.x + bb.x) * q.x;
        s += ((v.y - fmu) * rs * ww.y + bb.y) * q.y;
        s += ((v.z - fmu) * rs * ww.z + bb.z) * q.z;
        s += ((v.w - fmu) * rs * ww.w + bb.w) * q.w;
    }
#pragma unroll
    for (int off = 16; off; off >>= 1) s += __shfl_down_sync(0xffffffffu, s, off);
    if (lane == 0) {
        float val = 1.0f / (1.0f + __expf(-(s + b4[0])));
        int i = g_iu[gw], j = g_ju[gw];
        out[i * NN + j] = val;
        out[j * NN + i] = val;
    }
}

// ---------------- host launch ----------------
extern "C" void kernel_launch(void* const* d_in, const int* in_sizes, int n_in,
                              void* d_out, int out_size)
{
    const float* x    = (const float*)d_in[0];
    const float* hid  = (const float*)d_in[1];
    const float* Wih  = (const float*)d_in[2];
    const float* Whh  = (const float*)d_in[3];
    const float* bih  = (const float*)d_in[4];
    const float* bhh  = (const float*)d_in[5];
    const float* W1   = (const float*)d_in[6];
    const float* b1   = (const float*)d_in[7];
    const float* ln1w = (const float*)d_in[8];
    const float* ln1b = (const float*)d_in[9];
    const float* W2   = (const float*)d_in[10];
    const float* b2   = (const float*)d_in[11];
    const float* ln2w = (const float*)d_in[12];
    const float* ln2b = (const float*)d_in[13];
    const float* W3   = (const float*)d_in[14];
    const float* b3   = (const float*)d_in[15];
    const float* ln3w = (const float*)d_in[16];
    const float* ln3b = (const float*)d_in[17];
    const float* W4   = (const float*)d_in[18];
    const float* b4   = (const float*)d_in[19];
    float* out = (float*)d_out;

    float *p_gi, *p_gh, *p_y;
    __half *p_ahi, *p_bWhh, *p_bW1, *p_bW2, *p_bW3;
    cudaGetSymbolAddress((void**)&p_gi,   g_gi);
    cudaGetSymbolAddress((void**)&p_gh,   g_gh);
    cudaGetSymbolAddress((void**)&p_y,    g_y);
    cudaGetSymbolAddress((void**)&p_ahi,  g_ahi);
    cudaGetSymbolAddress((void**)&p_bWhh, g_bWhh);
    cudaGetSymbolAddress((void**)&p_bW1,  g_bW1);
    cudaGetSymbolAddress((void**)&p_bW2,  g_bW2);
    cudaGetSymbolAddress((void**)&p_bW3,  g_bW3);
    __half* p_ghh = (__half*)p_gh;
    float* p_t  = p_gh;
    float* p_t2 = p_gh + (size_t)PP * H2;

    cudaFuncSetAttribute(k_bgemm<false, -1, true>, cudaFuncAttributeMaxDynamicSharedMemorySize, GSMEM);
    cudaFuncSetAttribute(k_bgemm<true, 0, false>,  cudaFuncAttributeMaxDynamicSharedMemorySize, GSMEM);
    cudaFuncSetAttribute(k_bgemm<true, 1, false>,  cudaFuncAttributeMaxDynamicSharedMemorySize, GSMEM);
    cudaFuncSetAttribute(k_bgemm<true, 2, false>,  cudaFuncAttributeMaxDynamicSharedMemorySize, GSMEM);

    const int MB = (PP + 127) / 128;  // 28
    const int GRU_G = (PP * (HSZ / 8) + 255) / 256;

    // 0) fused init + all weight converts (single node)
    k_convall<<<(N8_ALL + 255) / 256, 256>>>((const float4*)Whh, (const float4*)W1,
                                             (const float4*)W2, (const float4*)W3);

    // 1) gi_node = x @ Wih^T + bih  [84, 6144], K=64 (tiny, f32 path)
    k_gemm<false, -1><<<dim3(G3H / 128, 1), 256>>>(x, Wih, bih, p_gi, NN, G3H, 64);

    // 2) GRU step 1
    k_conva8<<<(PP * HSZ / 8 + 255) / 256, 256>>>((const float4*)hid, (uint4*)p_ahi, PP * HSZ / 8);
    k_bgemm<false, -1, true><<<dim3(G3H / 128, MB), 128, GSMEM>>>(
        p_ahi, p_bWhh, bhh, p_ghh, PP, G3H, HSZ);
    k_gru<0><<<GRU_G, 256>>>(hid, p_ghh, (uint4*)p_ahi);

    // 3) GRU step 2
    k_bgemm<false, -1, true><<<dim3(G3H / 128, MB), 128, GSMEM>>>(
        p_ahi, p_bWhh, bhh, p_ghh, PP, G3H, HSZ);
    k_gru<1><<<GRU_G, 256>>>(hid, p_ghh, (uint4*)p_ahi);

    // 4) layer 1 + LN
    k_bgemm<true, 0, false><<<dim3(HSZ / 128, MB), 128, GSMEM>>>(
        p_ahi, p_bW1, b1, p_y, PP, HSZ, HSZ);
    k_norm<<<2048, 256>>>(p_y, ln1w, ln1b, PP * HSZ / 8, 0, (uint4*)p_ahi);

    // 5) layer 2 + LN
    k_bgemm<true, 1, false><<<dim3(H2 / 128, MB), 128, GSMEM>>>(
        p_ahi, p_bW2, b2, p_t, PP, H2, HSZ);
    k_norm<<<2048, 256>>>(p_t, ln2w, ln2b, PP * H2 / 8, 1, (uint4*)p_ahi);

    // 6) layer 3 (raw f32 out; LN fused into k_out)
    k_bgemm<true, 2, false><<<dim3(H2 / 128, MB), 128, GSMEM>>>(
        p_ahi, p_bW3, b3, p_t2, PP, H2, H2);

    // 7) output: fused LN3 + dot + sigmoid + symmetric scatter
    k_out<<<((PP + NN) * 32 + 255) / 256, 256>>>(p_t2, ln3w, ln3b, W4, b4, out);
}